// round 2
// baseline (speedup 1.0000x reference)
#include <cuda_runtime.h>
#include <cuda_bf16.h>
#include <math.h>

// Problem constants
#define B_SZ 4
#define T_SEQ 2048
#define D_MODEL 1024
#define NH 16
#define HD 64
#define QKV_STRIDE (3 * D_MODEL)   // 3072
#define M_ROWS (B_SZ * T_SEQ)      // 8192

// ---------------------------------------------------------------------------
// Scratch (device globals: no dynamic allocation allowed)
// ---------------------------------------------------------------------------
__device__ float g_qkv[(size_t)M_ROWS * QKV_STRIDE];   // [B*T, 3D]  ~100 MB
__device__ float g_ctx[(size_t)M_ROWS * D_MODEL];      // [B*T, D]   ~33 MB

// ---------------------------------------------------------------------------
// SGEMM with bias: C[M,N] = A[M,K] @ B[K,N] + bias[N]
// 128x128 block tile, BK=8, 256 threads, 8x8 per-thread microtile, float4 I/O.
// ---------------------------------------------------------------------------
#define BM 128
#define BN 128
#define BK 8
#define TM 8
#define TN 8

__global__ __launch_bounds__(256) void sgemm_bias_kernel(
    const float* __restrict__ A, const float* __restrict__ Bm,
    const float* __restrict__ bias, float* __restrict__ C,
    int M, int N, int K)
{
    __shared__ float As[BK][BM];
    __shared__ float Bs[BK][BN];

    const int tid  = threadIdx.x;
    const int brow = blockIdx.y * BM;
    const int bcol = blockIdx.x * BN;

    const int a_row = tid >> 1;          // 0..127
    const int a_col = (tid & 1) << 2;    // 0 or 4
    const int b_row = tid >> 5;          // 0..7
    const int b_col = (tid & 31) << 2;   // 0..124

    const int ty = tid >> 4;             // 0..15
    const int tx = tid & 15;             // 0..15

    float acc[TM][TN];
    #pragma unroll
    for (int i = 0; i < TM; i++)
        #pragma unroll
        for (int j = 0; j < TN; j++)
            acc[i][j] = 0.0f;

    const float* Aptr = A + (size_t)brow * K;
    const float* Bptr = Bm + bcol;

    for (int k0 = 0; k0 < K; k0 += BK) {
        float4 av = *(const float4*)(Aptr + (size_t)a_row * K + k0 + a_col);
        As[a_col + 0][a_row] = av.x;
        As[a_col + 1][a_row] = av.y;
        As[a_col + 2][a_row] = av.z;
        As[a_col + 3][a_row] = av.w;
        *(float4*)&Bs[b_row][b_col] =
            *(const float4*)(Bptr + (size_t)(k0 + b_row) * N + b_col);
        __syncthreads();

        #pragma unroll
        for (int k = 0; k < BK; k++) {
            float4 ra0 = *(const float4*)&As[k][ty * TM];
            float4 ra1 = *(const float4*)&As[k][ty * TM + 4];
            float4 rb0 = *(const float4*)&Bs[k][tx * TN];
            float4 rb1 = *(const float4*)&Bs[k][tx * TN + 4];
            float ra[TM] = {ra0.x, ra0.y, ra0.z, ra0.w, ra1.x, ra1.y, ra1.z, ra1.w};
            float rb[TN] = {rb0.x, rb0.y, rb0.z, rb0.w, rb1.x, rb1.y, rb1.z, rb1.w};
            #pragma unroll
            for (int i = 0; i < TM; i++)
                #pragma unroll
                for (int j = 0; j < TN; j++)
                    acc[i][j] += ra[i] * rb[j];
        }
        __syncthreads();
    }

    #pragma unroll
    for (int i = 0; i < TM; i++) {
        const int r = brow + ty * TM + i;
        #pragma unroll
        for (int j = 0; j < TN; j += 4) {
            const int c = bcol + tx * TN + j;
            float4 bv = *(const float4*)&bias[c];
            float4 o;
            o.x = acc[i][j + 0] + bv.x;
            o.y = acc[i][j + 1] + bv.y;
            o.z = acc[i][j + 2] + bv.z;
            o.w = acc[i][j + 3] + bv.w;
            *(float4*)&C[(size_t)r * N + c] = o;
        }
    }
}

// ---------------------------------------------------------------------------
// Attention: warp-per-query flash attention with online softmax.
// Mask input is int32 (bool promoted by harness): nonzero => masked.
// ---------------------------------------------------------------------------
#define WPB 8    // warps (= queries) per block
#define KT 32    // key-tile size
#define SPAD 4   // smem row padding (floats)

__global__ __launch_bounds__(WPB * 32) void attn_kernel(
    const float* __restrict__ qkv,
    const int* __restrict__ kpm,
    float* __restrict__ ctx)
{
    __shared__ float Ks[KT][HD + SPAD];
    __shared__ float Vs[KT][HD + SPAD];
    __shared__ float Qs[WPB][HD + SPAD];

    const int b    = blockIdx.z;
    const int h    = blockIdx.y;
    const int warp = threadIdx.x >> 5;
    const int lane = threadIdx.x & 31;
    const int q    = blockIdx.x * WPB + warp;

    const float scale_log2e = 0.125f * 1.4426950408889634f;  // (1/sqrt(64))*log2(e)

    {
        const float* qb = qkv + ((size_t)(b * T_SEQ + q)) * QKV_STRIDE + h * HD;
        Qs[warp][lane]      = qb[lane];
        Qs[warp][lane + 32] = qb[lane + 32];
        __syncwarp();
    }

    float acc0 = 0.0f, acc1 = 0.0f;
    float m = -1e30f, l = 0.0f;

    const int   limit   = q;  // causal: keys <= q
    const int   maxq    = blockIdx.x * WPB + (WPB - 1);
    const int   ntiles  = maxq / KT + 1;
    const float* kvbase = qkv + (size_t)b * T_SEQ * QKV_STRIDE + D_MODEL + h * HD;
    const int*  mrow    = kpm + (size_t)b * T_SEQ;

    for (int kt = 0; kt < ntiles; kt++) {
        __syncthreads();
        {
            const int r = threadIdx.x >> 3;        // 0..31
            const int c = (threadIdx.x & 7) << 3;  // 0..56 step 8
            const float* src = kvbase + (size_t)(kt * KT + r) * QKV_STRIDE + c;
            *(float4*)&Ks[r][c]     = *(const float4*)(src);
            *(float4*)&Ks[r][c + 4] = *(const float4*)(src + 4);
            *(float4*)&Vs[r][c]     = *(const float4*)(src + D_MODEL);
            *(float4*)&Vs[r][c + 4] = *(const float4*)(src + D_MODEL + 4);
        }
        __syncthreads();

        const int  kk    = kt * KT + lane;
        const bool valid = (kk <= limit) && (mrow[kk] == 0);

        float s = -1e30f;
        if (valid) {
            float4 sum = make_float4(0.f, 0.f, 0.f, 0.f);
            #pragma unroll
            for (int d = 0; d < HD; d += 4) {
                float4 qd = *(const float4*)&Qs[warp][d];
                float4 kd = *(const float4*)&Ks[lane][d];
                sum.x += qd.x * kd.x;
                sum.y += qd.y * kd.y;
                sum.z += qd.z * kd.z;
                sum.w += qd.w * kd.w;
            }
            s = (sum.x + sum.y + sum.z + sum.w) * scale_log2e;
        }

        float tile_m = s;
        #pragma unroll
        for (int o = 16; o > 0; o >>= 1)
            tile_m = fmaxf(tile_m, __shfl_xor_sync(0xffffffffu, tile_m, o));

        if (tile_m > -1e29f) {
            const float new_m  = fmaxf(m, tile_m);
            const float factor = exp2f(m - new_m);
            const float p      = exp2f(s - new_m);

            float psum = p;
            #pragma unroll
            for (int o = 16; o > 0; o >>= 1)
                psum += __shfl_xor_sync(0xffffffffu, psum, o);

            l    = l * factor + psum;
            acc0 *= factor;
            acc1 *= factor;

            #pragma unroll
            for (int j = 0; j < KT; j++) {
                const float pj = __shfl_sync(0xffffffffu, p, j);
                acc0 += pj * Vs[j][lane];
                acc1 += pj * Vs[j][lane + 32];
            }
            m = new_m;
        }
    }

    const float inv_l = 1.0f / l;
    float* out = ctx + ((size_t)(b * T_SEQ + q)) * D_MODEL + h * HD;
    out[lane]      = acc0 * inv_l;
    out[lane + 32] = acc1 * inv_l;
}

// ---------------------------------------------------------------------------
// Launch
// ---------------------------------------------------------------------------
extern "C" void kernel_launch(void* const* d_in, const int* in_sizes, int n_in,
                              void* d_out, int out_size)
{
    // Map inputs by element count (all distinct):
    // x:8388608, W_qkv:3145728, b_qkv:3072, W_o:1048576, b_o:1024, mask:8192
    const float* x = nullptr;
    const float* W_qkv = nullptr;
    const float* b_qkv = nullptr;
    const float* W_o = nullptr;
    const float* b_o = nullptr;
    const int*   kpm = nullptr;
    for (int i = 0; i < n_in; i++) {
        switch (in_sizes[i]) {
            case 8388608: x     = (const float*)d_in[i]; break;
            case 3145728: W_qkv = (const float*)d_in[i]; break;
            case 3072:    b_qkv = (const float*)d_in[i]; break;
            case 1048576: W_o   = (const float*)d_in[i]; break;
            case 1024:    b_o   = (const float*)d_in[i]; break;
            case 8192:    kpm   = (const int*)d_in[i]; break;
            default: break;
        }
    }
    float* out = (float*)d_out;

    float* qkv_ptr = nullptr;
    float* ctx_ptr = nullptr;
    cudaGetSymbolAddress((void**)&qkv_ptr, g_qkv);
    cudaGetSymbolAddress((void**)&ctx_ptr, g_ctx);

    // 1) QKV projection
    {
        dim3 grid(QKV_STRIDE / BN, M_ROWS / BM);
        sgemm_bias_kernel<<<grid, 256>>>(x, W_qkv, b_qkv, qkv_ptr,
                                         M_ROWS, QKV_STRIDE, D_MODEL);
    }
    // 2) Masked causal attention
    {
        dim3 grid(T_SEQ / WPB, NH, B_SZ);
        attn_kernel<<<grid, WPB * 32>>>(qkv_ptr, kpm, ctx_ptr);
    }
    // 3) Output projection
    {
        dim3 grid(D_MODEL / BN, M_ROWS / BM);
        sgemm_bias_kernel<<<grid, 256>>>(ctx_ptr, W_o, b_o, out,
                                         M_ROWS, D_MODEL, D_MODEL);
    }
}

// round 3
// speedup vs baseline: 5.8194x; 5.8194x over previous
#include <cuda_runtime.h>
#include <math.h>
#include <stdint.h>

#define B_SZ 4
#define T_SEQ 2048
#define D_MODEL 1024
#define NH 16
#define HD 64
#define QKV_STRIDE 3072
#define M_ROWS 8192

// Scratch (device globals: no dynamic allocation allowed)
__device__ float g_qkv[(size_t)M_ROWS * QKV_STRIDE];   // [B*T, 3D]
__device__ float g_ctx[(size_t)M_ROWS * D_MODEL];      // [B*T, D]

// ---------------------------------------------------------------------------
// tf32 helpers
// ---------------------------------------------------------------------------
__device__ __forceinline__ uint32_t f2tf(float f) {
    uint32_t u; asm("cvt.rna.tf32.f32 %0, %1;" : "=r"(u) : "f"(f)); return u;
}
__device__ __forceinline__ float ex2(float x) {
    float r; asm("ex2.approx.ftz.f32 %0, %1;" : "=f"(r) : "f"(x)); return r;
}
// D = A(16x8) * B(8x8) + D, tf32 inputs, fp32 accum.
__device__ __forceinline__ void mma_tf32(float* c, const uint32_t* a, const uint32_t* b) {
    asm volatile(
        "mma.sync.aligned.m16n8k8.row.col.f32.tf32.tf32.f32 "
        "{%0,%1,%2,%3},{%4,%5,%6,%7},{%8,%9},{%0,%1,%2,%3};"
        : "+f"(c[0]), "+f"(c[1]), "+f"(c[2]), "+f"(c[3])
        : "r"(a[0]), "r"(a[1]), "r"(a[2]), "r"(a[3]), "r"(b[0]), "r"(b[1]));
}

// ---------------------------------------------------------------------------
// TF32 GEMM + bias: C[M,N] = A[M,K]@B[K,N] + bias
// 128x128x16 block tile, 256 threads (8 warps as 2x4 of 64x32 warp tiles).
// ---------------------------------------------------------------------------
#define G_BM 128
#define G_BN 128
#define G_BK 16
#define G_LDA 20    // 20 % 32 == 20; bank(20*g + t) unique for g<8,t<4
#define G_LDB 136   // 136 % 32 == 8;  bank(8*t + g) unique

__global__ __launch_bounds__(256) void gemm_tf32(
    const float* __restrict__ A, const float* __restrict__ Bm,
    const float* __restrict__ bias, float* __restrict__ C,
    int M, int N, int K)
{
    __shared__ uint32_t As[G_BM * G_LDA];
    __shared__ uint32_t Bs[G_BK * G_LDB];

    const int tid  = threadIdx.x;
    const int lane = tid & 31, w = tid >> 5;
    const int g = lane >> 2, t = lane & 3;
    const int wm = (w >> 2) * 64, wn = (w & 3) * 32;
    const int brow = blockIdx.y * G_BM, bcol = blockIdx.x * G_BN;

    float acc[4][4][4];
    #pragma unroll
    for (int mt = 0; mt < 4; mt++)
        #pragma unroll
        for (int nt = 0; nt < 4; nt++)
            #pragma unroll
            for (int i = 0; i < 4; i++) acc[mt][nt][i] = 0.f;

    for (int k0 = 0; k0 < K; k0 += G_BK) {
        // A tile: 128x16 = 512 float4; 2 per thread
        #pragma unroll
        for (int i = 0; i < 2; i++) {
            int idx = tid + i * 256;
            int r = idx >> 2, cq = idx & 3;
            float4 v = *(const float4*)&A[(size_t)(brow + r) * K + k0 + cq * 4];
            uint4 u = make_uint4(f2tf(v.x), f2tf(v.y), f2tf(v.z), f2tf(v.w));
            *(uint4*)&As[r * G_LDA + cq * 4] = u;
        }
        // B tile: 16x128 = 512 float4; 2 per thread
        #pragma unroll
        for (int i = 0; i < 2; i++) {
            int idx = tid + i * 256;
            int r = idx >> 5, cq = idx & 31;
            float4 v = *(const float4*)&Bm[(size_t)(k0 + r) * N + bcol + cq * 4];
            uint4 u = make_uint4(f2tf(v.x), f2tf(v.y), f2tf(v.z), f2tf(v.w));
            *(uint4*)&Bs[r * G_LDB + cq * 4] = u;
        }
        __syncthreads();

        #pragma unroll
        for (int ks = 0; ks < 2; ks++) {
            uint32_t af[4][4], bf[4][2];
            #pragma unroll
            for (int mt = 0; mt < 4; mt++) {
                int row = wm + mt * 16;
                af[mt][0] = As[(row + g)     * G_LDA + ks * 8 + t];
                af[mt][1] = As[(row + g + 8) * G_LDA + ks * 8 + t];
                af[mt][2] = As[(row + g)     * G_LDA + ks * 8 + t + 4];
                af[mt][3] = As[(row + g + 8) * G_LDA + ks * 8 + t + 4];
            }
            #pragma unroll
            for (int nt = 0; nt < 4; nt++) {
                int col = wn + nt * 8 + g;
                bf[nt][0] = Bs[(ks * 8 + t)     * G_LDB + col];
                bf[nt][1] = Bs[(ks * 8 + t + 4) * G_LDB + col];
            }
            #pragma unroll
            for (int mt = 0; mt < 4; mt++)
                #pragma unroll
                for (int nt = 0; nt < 4; nt++)
                    mma_tf32(acc[mt][nt], af[mt], bf[nt]);
        }
        __syncthreads();
    }

    // Epilogue with bias
    #pragma unroll
    for (int mt = 0; mt < 4; mt++) {
        int r0 = brow + wm + mt * 16 + g;
        #pragma unroll
        for (int nt = 0; nt < 4; nt++) {
            int c = bcol + wn + nt * 8 + 2 * t;
            float2 bv = *(const float2*)&bias[c];
            float2 o0 = make_float2(acc[mt][nt][0] + bv.x, acc[mt][nt][1] + bv.y);
            float2 o1 = make_float2(acc[mt][nt][2] + bv.x, acc[mt][nt][3] + bv.y);
            *(float2*)&C[(size_t)r0 * N + c]       = o0;
            *(float2*)&C[(size_t)(r0 + 8) * N + c] = o1;
        }
    }
}

// ---------------------------------------------------------------------------
// FlashAttention-2 with tf32 mma.
// Block: one (b,h), 64 queries, 128 threads (4 warps x 16 query rows).
// Key tiles of 64. Online softmax in registers; P via smem (layout fixup).
// ---------------------------------------------------------------------------
#define AT_QT 64
#define AT_KT 64
#define LDK 68   // 68%32=4 : bank(4g+t) unique
#define LDV 72   // 72%32=8 : bank(8t+g) unique
#define LDP 68

__global__ __launch_bounds__(128) void attn_tf32(
    const float* __restrict__ qkv, const int* __restrict__ kpm,
    float* __restrict__ ctx)
{
    extern __shared__ uint32_t smem_u[];
    uint32_t* Ks = smem_u;                 // 64*LDK
    uint32_t* Vs = Ks + 64 * LDK;          // 64*LDV
    uint32_t* Ps = Vs + 64 * LDV;          // 64*LDP
    float*    mb = (float*)(Ps + 64 * LDP);// 64

    const int tid = threadIdx.x, lane = tid & 31, w = tid >> 5;
    const int g = lane >> 2, t = lane & 3;
    const int b = blockIdx.z, h = blockIdx.y;
    const int qb = blockIdx.x * AT_QT;

    // Q fragments (held in registers for the entire block)
    uint32_t qf[8][4];
    {
        const float* qp = qkv + ((size_t)(b * T_SEQ + qb + w * 16)) * QKV_STRIDE + h * HD;
        #pragma unroll
        for (int ks = 0; ks < 8; ks++) {
            int c = ks * 8 + t;
            qf[ks][0] = f2tf(qp[(size_t)g       * QKV_STRIDE + c]);
            qf[ks][1] = f2tf(qp[(size_t)(g + 8) * QKV_STRIDE + c]);
            qf[ks][2] = f2tf(qp[(size_t)g       * QKV_STRIDE + c + 4]);
            qf[ks][3] = f2tf(qp[(size_t)(g + 8) * QKV_STRIDE + c + 4]);
        }
    }

    float o[8][4];
    #pragma unroll
    for (int nt = 0; nt < 8; nt++)
        #pragma unroll
        for (int i = 0; i < 4; i++) o[nt][i] = 0.f;

    float m0 = -1e30f, m1 = -1e30f, l0 = 0.f, l1 = 0.f;
    const int q0 = qb + w * 16 + g, q1 = q0 + 8;
    const float SL = 0.125f * 1.4426950408889634f;   // scale * log2(e)
    const float* kvb = qkv + (size_t)b * T_SEQ * QKV_STRIDE + D_MODEL + h * HD;
    const int* mrow = kpm + b * T_SEQ;

    const int ntiles = blockIdx.x + 1;
    for (int kt = 0; kt < ntiles; kt++) {
        const int kb = kt * AT_KT;
        __syncthreads();
        // K/V tile load with tf32 conversion: 64 rows x 16 float4 each
        #pragma unroll
        for (int i = 0; i < 8; i++) {
            int idx = tid + i * 128;
            int r = idx >> 4, cq = idx & 15;
            const float* src = kvb + (size_t)(kb + r) * QKV_STRIDE + cq * 4;
            float4 kv = *(const float4*)src;
            float4 vv = *(const float4*)(src + D_MODEL);
            *(uint4*)&Ks[r * LDK + cq * 4] =
                make_uint4(f2tf(kv.x), f2tf(kv.y), f2tf(kv.z), f2tf(kv.w));
            *(uint4*)&Vs[r * LDV + cq * 4] =
                make_uint4(f2tf(vv.x), f2tf(vv.y), f2tf(vv.z), f2tf(vv.w));
        }
        if (tid < AT_KT) mb[tid] = mrow[kb + tid] ? -1e30f : 0.f;
        __syncthreads();

        // S = Q @ K^T  (per warp: 16 x 64)
        float s[8][4];
        #pragma unroll
        for (int nt = 0; nt < 8; nt++) {
            s[nt][0] = s[nt][1] = s[nt][2] = s[nt][3] = 0.f;
            #pragma unroll
            for (int ks = 0; ks < 8; ks++) {
                uint32_t bf[2];
                bf[0] = Ks[(nt * 8 + g) * LDK + ks * 8 + t];
                bf[1] = Ks[(nt * 8 + g) * LDK + ks * 8 + t + 4];
                mma_tf32(s[nt], qf[ks], bf);
            }
        }

        // mask + scale + row max
        float mx0 = -1e30f, mx1 = -1e30f;
        #pragma unroll
        for (int nt = 0; nt < 8; nt++) {
            int cl = nt * 8 + 2 * t;
            float mb0 = mb[cl], mb1 = mb[cl + 1];
            int k0c = kb + cl, k1c = k0c + 1;
            float v00 = s[nt][0] * SL + mb0; if (k0c > q0) v00 = -1e30f;
            float v01 = s[nt][1] * SL + mb1; if (k1c > q0) v01 = -1e30f;
            float v10 = s[nt][2] * SL + mb0; if (k0c > q1) v10 = -1e30f;
            float v11 = s[nt][3] * SL + mb1; if (k1c > q1) v11 = -1e30f;
            s[nt][0] = v00; s[nt][1] = v01; s[nt][2] = v10; s[nt][3] = v11;
            mx0 = fmaxf(mx0, fmaxf(v00, v01));
            mx1 = fmaxf(mx1, fmaxf(v10, v11));
        }
        mx0 = fmaxf(mx0, __shfl_xor_sync(0xffffffffu, mx0, 1));
        mx0 = fmaxf(mx0, __shfl_xor_sync(0xffffffffu, mx0, 2));
        mx1 = fmaxf(mx1, __shfl_xor_sync(0xffffffffu, mx1, 1));
        mx1 = fmaxf(mx1, __shfl_xor_sync(0xffffffffu, mx1, 2));

        const float nm0 = fmaxf(m0, mx0), nm1 = fmaxf(m1, mx1);
        const float f0 = ex2(m0 - nm0), f1 = ex2(m1 - nm1);

        // P = exp2(S - m), accumulate row sums, store P (tf32) to smem
        float sum0 = 0.f, sum1 = 0.f;
        const int pr0 = w * 16 + g, pr1 = pr0 + 8;
        #pragma unroll
        for (int nt = 0; nt < 8; nt++) {
            float p00 = ex2(s[nt][0] - nm0);
            float p01 = ex2(s[nt][1] - nm0);
            float p10 = ex2(s[nt][2] - nm1);
            float p11 = ex2(s[nt][3] - nm1);
            sum0 += p00 + p01; sum1 += p10 + p11;
            *(uint2*)&Ps[pr0 * LDP + nt * 8 + 2 * t] = make_uint2(f2tf(p00), f2tf(p01));
            *(uint2*)&Ps[pr1 * LDP + nt * 8 + 2 * t] = make_uint2(f2tf(p10), f2tf(p11));
        }
        sum0 += __shfl_xor_sync(0xffffffffu, sum0, 1);
        sum0 += __shfl_xor_sync(0xffffffffu, sum0, 2);
        sum1 += __shfl_xor_sync(0xffffffffu, sum1, 1);
        sum1 += __shfl_xor_sync(0xffffffffu, sum1, 2);
        l0 = l0 * f0 + sum0;
        l1 = l1 * f1 + sum1;

        // rescale O accumulator
        #pragma unroll
        for (int nt = 0; nt < 8; nt++) {
            o[nt][0] *= f0; o[nt][1] *= f0; o[nt][2] *= f1; o[nt][3] *= f1;
        }
        m0 = nm0; m1 = nm1;
        __syncwarp();

        // O += P @ V  (per warp: 16x64 += (16x64)@(64x64))
        #pragma unroll
        for (int ks = 0; ks < 8; ks++) {
            uint32_t af[4];
            af[0] = Ps[pr0 * LDP + ks * 8 + t];
            af[1] = Ps[pr1 * LDP + ks * 8 + t];
            af[2] = Ps[pr0 * LDP + ks * 8 + t + 4];
            af[3] = Ps[pr1 * LDP + ks * 8 + t + 4];
            #pragma unroll
            for (int nt = 0; nt < 8; nt++) {
                uint32_t bf[2];
                bf[0] = Vs[(ks * 8 + t)     * LDV + nt * 8 + g];
                bf[1] = Vs[(ks * 8 + t + 4) * LDV + nt * 8 + g];
                mma_tf32(o[nt], af, bf);
            }
        }
    }

    // Normalize and write ctx [B*T, H*HD]
    const float i0 = 1.f / l0, i1 = 1.f / l1;
    float* op = ctx + (size_t)b * T_SEQ * D_MODEL + h * HD;
    #pragma unroll
    for (int nt = 0; nt < 8; nt++) {
        int c = nt * 8 + 2 * t;
        *(float2*)&op[(size_t)q0 * D_MODEL + c] =
            make_float2(o[nt][0] * i0, o[nt][1] * i0);
        *(float2*)&op[(size_t)q1 * D_MODEL + c] =
            make_float2(o[nt][2] * i1, o[nt][3] * i1);
    }
}

// ---------------------------------------------------------------------------
// Launch
// ---------------------------------------------------------------------------
#define ATTN_SMEM ((64 * LDK + 64 * LDV + 64 * LDP) * 4 + 64 * 4)

extern "C" void kernel_launch(void* const* d_in, const int* in_sizes, int n_in,
                              void* d_out, int out_size)
{
    const float* x = nullptr;
    const float* W_qkv = nullptr;
    const float* b_qkv = nullptr;
    const float* W_o = nullptr;
    const float* b_o = nullptr;
    const int*   kpm = nullptr;
    for (int i = 0; i < n_in; i++) {
        switch (in_sizes[i]) {
            case 8388608: x     = (const float*)d_in[i]; break;
            case 3145728: W_qkv = (const float*)d_in[i]; break;
            case 3072:    b_qkv = (const float*)d_in[i]; break;
            case 1048576: W_o   = (const float*)d_in[i]; break;
            case 1024:    b_o   = (const float*)d_in[i]; break;
            case 8192:    kpm   = (const int*)d_in[i]; break;
            default: break;
        }
    }
    float* out = (float*)d_out;

    float* qkv_ptr = nullptr;
    float* ctx_ptr = nullptr;
    cudaGetSymbolAddress((void**)&qkv_ptr, g_qkv);
    cudaGetSymbolAddress((void**)&ctx_ptr, g_ctx);

    cudaFuncSetAttribute(attn_tf32, cudaFuncAttributeMaxDynamicSharedMemorySize,
                         ATTN_SMEM);

    // 1) QKV projection
    {
        dim3 grid(QKV_STRIDE / G_BN, M_ROWS / G_BM);
        gemm_tf32<<<grid, 256>>>(x, W_qkv, b_qkv, qkv_ptr,
                                 M_ROWS, QKV_STRIDE, D_MODEL);
    }
    // 2) FlashAttention (tf32 tensor cores)
    {
        dim3 grid(T_SEQ / AT_QT, NH, B_SZ);
        attn_tf32<<<grid, 128, ATTN_SMEM>>>(qkv_ptr, kpm, ctx_ptr);
    }
    // 3) Output projection
    {
        dim3 grid(D_MODEL / G_BN, M_ROWS / G_BM);
        gemm_tf32<<<grid, 256>>>(ctx_ptr, W_o, b_o, out,
                                 M_ROWS, D_MODEL, D_MODEL);
    }
}

// round 6
// speedup vs baseline: 13.1950x; 2.2674x over previous
#include <cuda_runtime.h>
#include <cuda_fp16.h>
#include <math.h>
#include <stdint.h>
#include <string.h>

#define B_SZ 4
#define T_SEQ 2048
#define D_MODEL 1024
#define NH 16
#define HD 64
#define QKV_STRIDE 3072
#define M_ROWS 8192

// ---------------------------------------------------------------------------
// Scratch (device globals: no dynamic allocation allowed)
// ---------------------------------------------------------------------------
__device__ __half g_xh   [(size_t)M_ROWS * D_MODEL];
__device__ __half g_wqkvh[(size_t)D_MODEL * QKV_STRIDE];
__device__ __half g_woh  [(size_t)D_MODEL * D_MODEL];
__device__ __half g_qkvh [(size_t)M_ROWS * QKV_STRIDE];
__device__ __half g_ctxh [(size_t)M_ROWS * D_MODEL];

// ---------------------------------------------------------------------------
// PTX helpers
// ---------------------------------------------------------------------------
__device__ __forceinline__ float ex2(float x) {
    float r; asm("ex2.approx.ftz.f32 %0, %1;" : "=f"(r) : "f"(x)); return r;
}
__device__ __forceinline__ uint32_t h2u(__half2 h) {
    uint32_t u; memcpy(&u, &h, 4); return u;
}
__device__ __forceinline__ void mma_f16(float* c, const uint32_t* a, const uint32_t* b) {
    asm volatile(
        "mma.sync.aligned.m16n8k16.row.col.f32.f16.f16.f32 "
        "{%0,%1,%2,%3},{%4,%5,%6,%7},{%8,%9},{%0,%1,%2,%3};"
        : "+f"(c[0]), "+f"(c[1]), "+f"(c[2]), "+f"(c[3])
        : "r"(a[0]), "r"(a[1]), "r"(a[2]), "r"(a[3]), "r"(b[0]), "r"(b[1]));
}
__device__ __forceinline__ void ldsm_x4(uint32_t* r, uint32_t addr) {
    asm volatile("ldmatrix.sync.aligned.m8n8.x4.shared.b16 {%0,%1,%2,%3}, [%4];"
                 : "=r"(r[0]), "=r"(r[1]), "=r"(r[2]), "=r"(r[3]) : "r"(addr));
}
__device__ __forceinline__ void ldsm_x4_t(uint32_t* r, uint32_t addr) {
    asm volatile("ldmatrix.sync.aligned.m8n8.x4.trans.shared.b16 {%0,%1,%2,%3}, [%4];"
                 : "=r"(r[0]), "=r"(r[1]), "=r"(r[2]), "=r"(r[3]) : "r"(addr));
}
__device__ __forceinline__ void cpa16(uint32_t dst, const void* src) {
    asm volatile("cp.async.cg.shared.global [%0], [%1], 16;" :: "r"(dst), "l"(src));
}
__device__ __forceinline__ void cpa_commit() { asm volatile("cp.async.commit_group;"); }
template<int N> __device__ __forceinline__ void cpa_wait() {
    asm volatile("cp.async.wait_group %0;" :: "n"(N));
}
__device__ __forceinline__ uint32_t s2u(const void* p) {
    return (uint32_t)__cvta_generic_to_shared(p);
}

// ---------------------------------------------------------------------------
// fp32 -> fp16 conversion
// ---------------------------------------------------------------------------
__global__ void conv_f2h(const float* __restrict__ in, __half2* __restrict__ out, int n2) {
    int i = blockIdx.x * blockDim.x + threadIdx.x;
    if (i < n2) {
        float2 v = ((const float2*)in)[i];
        out[i] = __floats2half2_rn(v.x, v.y);
    }
}

// ---------------------------------------------------------------------------
// fp16 GEMM + bias: C[M,N] = A[M,K]@B[K,N] + bias.  A,B fp16; accum fp32.
// 128x128x32 tile, 256 threads (8 warps as 2x4 of 64x32), 3-stage cp.async.
// ---------------------------------------------------------------------------
#define G_BM 128
#define G_BN 128
#define G_BK 32
#define LDA_B 80      // A row stride bytes (32 halves + 8 pad)
#define LDB_B 272     // B row stride bytes (128 halves + 8 pad)
#define A_STG (G_BM * LDA_B)              // 10240
#define B_STG (G_BK * LDB_B)              // 8704
#define STG_B (A_STG + B_STG)             // 18944
#define G_SMEM (3 * STG_B)                // 56832

template<int OUT_HALF>
__global__ __launch_bounds__(256, 2) void gemm_h(
    const __half* __restrict__ A, const __half* __restrict__ Bm,
    const float* __restrict__ bias, void* __restrict__ Cout,
    int M, int N, int K)
{
    extern __shared__ char smem[];
    const int tid  = threadIdx.x;
    const int lane = tid & 31, w = tid >> 5;
    const int g = lane >> 2, t = lane & 3;
    const int lrow = lane & 7, seg = lane >> 3;
    const int wm = (w >> 2) * 64, wn = (w & 3) * 32;
    const int brow = blockIdx.y * G_BM, bcol = blockIdx.x * G_BN;
    const int NIT = K / G_BK;

    auto prefetch = [&](int it, int s) {
        char* As = smem + s * STG_B;
        char* Bs = As + A_STG;
        const int k0 = it * G_BK;
        #pragma unroll
        for (int i = 0; i < 2; i++) {   // A: 512 x 16B chunks
            int idx = tid + i * 256;
            int r = idx >> 2, c = idx & 3;
            cpa16(s2u(As + r * LDA_B + c * 16),
                  A + (size_t)(brow + r) * K + k0 + c * 8);
        }
        #pragma unroll
        for (int i = 0; i < 2; i++) {   // B: 512 x 16B chunks
            int idx = tid + i * 256;
            int r = idx >> 4, c = idx & 15;
            cpa16(s2u(Bs + r * LDB_B + c * 16),
                  Bm + (size_t)(k0 + r) * N + bcol + c * 8);
        }
        cpa_commit();
    };

    float acc[4][4][4];
    #pragma unroll
    for (int mt = 0; mt < 4; mt++)
        #pragma unroll
        for (int nt = 0; nt < 4; nt++)
            #pragma unroll
            for (int i = 0; i < 4; i++) acc[mt][nt][i] = 0.f;

    prefetch(0, 0);
    prefetch(1, 1);

    for (int it = 0; it < NIT; it++) {
        cpa_wait<1>();
        __syncthreads();
        if (it + 2 < NIT) prefetch(it + 2, (it + 2) % 3);

        char* As = smem + (it % 3) * STG_B;
        char* Bs = As + A_STG;

        #pragma unroll
        for (int ks = 0; ks < 2; ks++) {
            uint32_t af[4][4], bf[4][2];
            #pragma unroll
            for (int mt = 0; mt < 4; mt++) {
                int row = wm + mt * 16 + ((seg & 1) ? 8 : 0) + lrow;
                int kk  = ks * 16 + ((seg >> 1) ? 8 : 0);
                ldsm_x4(af[mt], s2u(As + row * LDA_B + kk * 2));
            }
            #pragma unroll
            for (int np = 0; np < 2; np++) {
                uint32_t r4[4];
                int kr = ks * 16 + ((seg & 1) ? 8 : 0) + lrow;
                int nc = wn + (np * 2 + (seg >> 1)) * 8;
                ldsm_x4_t(r4, s2u(Bs + kr * LDB_B + nc * 2));
                bf[np * 2][0] = r4[0]; bf[np * 2][1] = r4[1];
                bf[np * 2 + 1][0] = r4[2]; bf[np * 2 + 1][1] = r4[3];
            }
            #pragma unroll
            for (int mt = 0; mt < 4; mt++)
                #pragma unroll
                for (int nt = 0; nt < 4; nt++)
                    mma_f16(acc[mt][nt], af[mt], bf[nt]);
        }
        __syncthreads();
    }

    // Epilogue with bias
    #pragma unroll
    for (int mt = 0; mt < 4; mt++) {
        int r0 = brow + wm + mt * 16 + g;
        #pragma unroll
        for (int nt = 0; nt < 4; nt++) {
            int c = bcol + wn + nt * 8 + 2 * t;
            float2 bv = *(const float2*)&bias[c];
            if (OUT_HALF) {
                __half2* C = (__half2*)Cout;
                C[((size_t)r0 * N + c) >> 1] =
                    __floats2half2_rn(acc[mt][nt][0] + bv.x, acc[mt][nt][1] + bv.y);
                C[((size_t)(r0 + 8) * N + c) >> 1] =
                    __floats2half2_rn(acc[mt][nt][2] + bv.x, acc[mt][nt][3] + bv.y);
            } else {
                float* C = (float*)Cout;
                *(float2*)&C[(size_t)r0 * N + c] =
                    make_float2(acc[mt][nt][0] + bv.x, acc[mt][nt][1] + bv.y);
                *(float2*)&C[(size_t)(r0 + 8) * N + c] =
                    make_float2(acc[mt][nt][2] + bv.x, acc[mt][nt][3] + bv.y);
            }
        }
    }
}

// ---------------------------------------------------------------------------
// FlashAttention-2, fp16 mma, P kept in registers, 2-stage cp.async K/V.
// Block: one (b,h), 64 queries, 128 threads (4 warps x 16 rows).
// ---------------------------------------------------------------------------
#define LDQ_B 144            // 64 halves + 8 pad
#define Q_SZ  (64 * LDQ_B)   // 9216
#define KV_SZ (2 * Q_SZ)     // 18432
#define AT_SMEM (Q_SZ + 2 * KV_SZ + 2 * 256)

__global__ __launch_bounds__(128) void attn_h(
    const __half* __restrict__ qkv, const int* __restrict__ kpm,
    __half* __restrict__ ctx)
{
    extern __shared__ char smem[];
    char* Qs  = smem;
    char* KV0 = smem + Q_SZ;
    char* MB  = smem + Q_SZ + 2 * KV_SZ;

    const int tid = threadIdx.x, lane = tid & 31, w = tid >> 5;
    const int g = lane >> 2, t = lane & 3;
    const int lrow = lane & 7, seg = lane >> 3;
    const int b = blockIdx.z, h = blockIdx.y;
    const int qb = blockIdx.x * 64;
    const int ntiles = blockIdx.x + 1;

    const __half* kvb = qkv + (size_t)b * T_SEQ * QKV_STRIDE + h * HD;
    const int* mrow = kpm + b * T_SEQ;

    auto prefetch = [&](int kt, int s) {
        char* K = KV0 + s * KV_SZ;
        const int kb = kt * 64;
        #pragma unroll
        for (int i = 0; i < 8; i++) {
            int idx = tid + i * 128;
            int isV = idx >> 9;
            int r = (idx & 511) >> 3, c = idx & 7;
            cpa16(s2u(K + isV * Q_SZ + r * LDQ_B + c * 16),
                  kvb + (size_t)(kb + r) * QKV_STRIDE + D_MODEL + isV * D_MODEL + c * 8);
        }
        if (tid < 16)
            cpa16(s2u(MB + s * 256 + tid * 16), mrow + kb + tid * 4);
        cpa_commit();
    };

    prefetch(0, 0);

    // Q tile -> smem (plain), then ldmatrix into persistent regs
    #pragma unroll
    for (int i = 0; i < 4; i++) {
        int idx = tid + i * 128;
        int r = idx >> 3, c = idx & 7;
        *(uint4*)(Qs + r * LDQ_B + c * 16) =
            *(const uint4*)(kvb + (size_t)(qb + r) * QKV_STRIDE + c * 8);
    }
    __syncthreads();
    uint32_t qf[4][4];
    #pragma unroll
    for (int kc = 0; kc < 4; kc++) {
        int row = w * 16 + ((seg & 1) ? 8 : 0) + lrow;
        int kk  = kc * 16 + ((seg >> 1) ? 8 : 0);
        ldsm_x4(qf[kc], s2u(Qs + row * LDQ_B + kk * 2));
    }

    float o[8][4];
    #pragma unroll
    for (int nt = 0; nt < 8; nt++)
        #pragma unroll
        for (int i = 0; i < 4; i++) o[nt][i] = 0.f;

    float m0 = -1e30f, m1 = -1e30f, l0 = 0.f, l1 = 0.f;
    const int q0 = qb + w * 16 + g, q1 = q0 + 8;
    const float SL = 0.125f * 1.4426950408889634f;

    for (int kt = 0; kt < ntiles; kt++) {
        cpa_wait<0>();
        __syncthreads();
        if (kt + 1 < ntiles) prefetch(kt + 1, (kt + 1) & 1);

        char* Ks = KV0 + (kt & 1) * KV_SZ;
        char* Vs = Ks + Q_SZ;
        const int* mb = (const int*)(MB + (kt & 1) * 256);
        const int kb = kt * 64;

        // S = Q @ K^T
        // B-fragment via non-trans ldmatrix on K[key][d]:
        // matrix order must be (key+0,d_lo),(key+0,d_hi),(key+8,d_lo),(key+8,d_hi)
        // => seg&1 advances d (k-dim), seg>>1 advances key (n-dim).
        float s[8][4];
        #pragma unroll
        for (int nt = 0; nt < 8; nt++)
            s[nt][0] = s[nt][1] = s[nt][2] = s[nt][3] = 0.f;
        #pragma unroll
        for (int kc = 0; kc < 4; kc++) {
            #pragma unroll
            for (int np = 0; np < 4; np++) {
                uint32_t r4[4];
                int krow = np * 16 + ((seg >> 1) ? 8 : 0) + lrow;   // key index
                int kk   = kc * 16 + ((seg & 1) ? 8 : 0);           // d index
                ldsm_x4(r4, s2u(Ks + krow * LDQ_B + kk * 2));
                uint32_t b0[2] = {r4[0], r4[1]}, b1[2] = {r4[2], r4[3]};
                mma_f16(s[np * 2],     qf[kc], b0);
                mma_f16(s[np * 2 + 1], qf[kc], b1);
            }
        }

        // mask + scale + row max
        float mx0 = -1e30f, mx1 = -1e30f;
        #pragma unroll
        for (int nt = 0; nt < 8; nt++) {
            int cl = nt * 8 + 2 * t;
            float a0 = mb[cl]     ? -1e30f : 0.f;
            float a1 = mb[cl + 1] ? -1e30f : 0.f;
            int k0c = kb + cl, k1c = k0c + 1;
            float v00 = s[nt][0] * SL + a0; if (k0c > q0) v00 = -1e30f;
            float v01 = s[nt][1] * SL + a1; if (k1c > q0) v01 = -1e30f;
            float v10 = s[nt][2] * SL + a0; if (k0c > q1) v10 = -1e30f;
            float v11 = s[nt][3] * SL + a1; if (k1c > q1) v11 = -1e30f;
            s[nt][0] = v00; s[nt][1] = v01; s[nt][2] = v10; s[nt][3] = v11;
            mx0 = fmaxf(mx0, fmaxf(v00, v01));
            mx1 = fmaxf(mx1, fmaxf(v10, v11));
        }
        mx0 = fmaxf(mx0, __shfl_xor_sync(0xffffffffu, mx0, 1));
        mx0 = fmaxf(mx0, __shfl_xor_sync(0xffffffffu, mx0, 2));
        mx1 = fmaxf(mx1, __shfl_xor_sync(0xffffffffu, mx1, 1));
        mx1 = fmaxf(mx1, __shfl_xor_sync(0xffffffffu, mx1, 2));

        const float nm0 = fmaxf(m0, mx0), nm1 = fmaxf(m1, mx1);
        const float f0 = ex2(m0 - nm0), f1 = ex2(m1 - nm1);

        // P = exp2(S - m) -> fp16 pairs (= A-fragments of P@V directly)
        uint32_t plo[8], phi[8];
        float sum0 = 0.f, sum1 = 0.f;
        #pragma unroll
        for (int nt = 0; nt < 8; nt++) {
            float p00 = ex2(s[nt][0] - nm0);
            float p01 = ex2(s[nt][1] - nm0);
            float p10 = ex2(s[nt][2] - nm1);
            float p11 = ex2(s[nt][3] - nm1);
            sum0 += p00 + p01; sum1 += p10 + p11;
            plo[nt] = h2u(__floats2half2_rn(p00, p01));
            phi[nt] = h2u(__floats2half2_rn(p10, p11));
        }
        sum0 += __shfl_xor_sync(0xffffffffu, sum0, 1);
        sum0 += __shfl_xor_sync(0xffffffffu, sum0, 2);
        sum1 += __shfl_xor_sync(0xffffffffu, sum1, 1);
        sum1 += __shfl_xor_sync(0xffffffffu, sum1, 2);
        l0 = l0 * f0 + sum0;
        l1 = l1 * f1 + sum1;
        #pragma unroll
        for (int nt = 0; nt < 8; nt++) {
            o[nt][0] *= f0; o[nt][1] *= f0; o[nt][2] *= f1; o[nt][3] *= f1;
        }
        m0 = nm0; m1 = nm1;

        // O += P @ V   (V[key][d], trans ldmatrix; key = k-dim, d = n-dim)
        #pragma unroll
        for (int kc = 0; kc < 4; kc++) {
            uint32_t af[4] = {plo[kc * 2], phi[kc * 2], plo[kc * 2 + 1], phi[kc * 2 + 1]};
            #pragma unroll
            for (int np = 0; np < 4; np++) {
                uint32_t r4[4];
                int krow = kc * 16 + ((seg & 1) ? 8 : 0) + lrow;
                int nc   = (np * 2 + (seg >> 1)) * 8;
                ldsm_x4_t(r4, s2u(Vs + krow * LDQ_B + nc * 2));
                uint32_t b0[2] = {r4[0], r4[1]}, b1[2] = {r4[2], r4[3]};
                mma_f16(o[np * 2],     af, b0);
                mma_f16(o[np * 2 + 1], af, b1);
            }
        }
    }

    // Normalize, write fp16 ctx [B*T, D]
    const float i0 = 1.f / l0, i1 = 1.f / l1;
    __half* op = ctx + (size_t)b * T_SEQ * D_MODEL + h * HD;
    #pragma unroll
    for (int nt = 0; nt < 8; nt++) {
        int c = nt * 8 + 2 * t;
        *(__half2*)(op + (size_t)q0 * D_MODEL + c) =
            __floats2half2_rn(o[nt][0] * i0, o[nt][1] * i0);
        *(__half2*)(op + (size_t)q1 * D_MODEL + c) =
            __floats2half2_rn(o[nt][2] * i1, o[nt][3] * i1);
    }
}

// ---------------------------------------------------------------------------
// Launch
// ---------------------------------------------------------------------------
extern "C" void kernel_launch(void* const* d_in, const int* in_sizes, int n_in,
                              void* d_out, int out_size)
{
    const float* x = nullptr; const float* W_qkv = nullptr;
    const float* b_qkv = nullptr; const float* W_o = nullptr;
    const float* b_o = nullptr; const int* kpm = nullptr;
    for (int i = 0; i < n_in; i++) {
        switch (in_sizes[i]) {
            case 8388608: x     = (const float*)d_in[i]; break;
            case 3145728: W_qkv = (const float*)d_in[i]; break;
            case 3072:    b_qkv = (const float*)d_in[i]; break;
            case 1048576: W_o   = (const float*)d_in[i]; break;
            case 1024:    b_o   = (const float*)d_in[i]; break;
            case 8192:    kpm   = (const int*)d_in[i]; break;
            default: break;
        }
    }
    float* out = (float*)d_out;

    __half *xh, *wqkvh, *woh, *qkvh, *ctxh;
    cudaGetSymbolAddress((void**)&xh, g_xh);
    cudaGetSymbolAddress((void**)&wqkvh, g_wqkvh);
    cudaGetSymbolAddress((void**)&woh, g_woh);
    cudaGetSymbolAddress((void**)&qkvh, g_qkvh);
    cudaGetSymbolAddress((void**)&ctxh, g_ctxh);

    static int attr_done = 0;
    if (!attr_done) {
        cudaFuncSetAttribute(gemm_h<1>, cudaFuncAttributeMaxDynamicSharedMemorySize, G_SMEM);
        cudaFuncSetAttribute(gemm_h<0>, cudaFuncAttributeMaxDynamicSharedMemorySize, G_SMEM);
        cudaFuncSetAttribute(attn_h, cudaFuncAttributeMaxDynamicSharedMemorySize, AT_SMEM);
        attr_done = 1;
    }

    // 0) fp32 -> fp16 conversions
    conv_f2h<<<(8388608 / 2 + 255) / 256, 256>>>(x, (__half2*)xh, 8388608 / 2);
    conv_f2h<<<(3145728 / 2 + 255) / 256, 256>>>(W_qkv, (__half2*)wqkvh, 3145728 / 2);
    conv_f2h<<<(1048576 / 2 + 255) / 256, 256>>>(W_o, (__half2*)woh, 1048576 / 2);

    // 1) QKV projection (fp16 out)
    {
        dim3 grid(QKV_STRIDE / G_BN, M_ROWS / G_BM);
        gemm_h<1><<<grid, 256, G_SMEM>>>(xh, wqkvh, b_qkv, qkvh,
                                         M_ROWS, QKV_STRIDE, D_MODEL);
    }
    // 2) FlashAttention
    {
        dim3 grid(T_SEQ / 64, NH, B_SZ);
        attn_h<<<grid, 128, AT_SMEM>>>(qkvh, kpm, ctxh);
    }
    // 3) Output projection (fp32 out)
    {
        dim3 grid(D_MODEL / G_BN, M_ROWS / G_BM);
        gemm_h<0><<<grid, 256, G_SMEM>>>(ctxh, woh, b_o, out,
                                         M_ROWS, D_MODEL, D_MODEL);
    }
}